// round 12
// baseline (speedup 1.0000x reference)
#include <cuda_runtime.h>
#include <cstdint>

// Problem dims
#define Bv 32
#define Cv 1024
#define Nv 784
#define Mv 4
#define N4v 196      // Nv/4
#define RW 8         // rows per warp
#define WB 4         // warps per block
#define BROWS (RW * WB)   // 32 rows per block
#define CHUNKS (Cv / BROWS)  // 32

// Scratch (device globals — zero-initialized at load; kC restores zeros)
__device__ float  g_invnorm[Bv][Cv];
__device__ float4 g_t[Bv][Mv][N4v];   // RED-accumulated t (400 KB)
__device__ float4 g_h[Bv][N4v];       // h[b,n] = sum_m g/s

extern __shared__ float4 sdyn[];      // [WB][Mv*N4v] = 4*784 float4 = 50176 B

// ---------------------------------------------------------------------------
// kAB: register-resident single pass. Warp owns a row: lane l holds quads
// l, l+32..l+192 in 7 float4 regs. Norm comes from those regs (shfl reduce);
// wsc is 4 scalars; accumulation goes into per-lane acc[4][7] registers that
// persist across the warp's 8 rows. NO smem / barriers in the main loop.
// Epilogue: one barrier, block smem-reduce of the 4 warps' acc, scalar
// atomic flush into g_t.
// ---------------------------------------------------------------------------
__global__ void __launch_bounds__(128) kAB(const float* __restrict__ x,
                                           const float* __restrict__ Wm) {
    int b = blockIdx.x, ch = blockIdx.y;
    int warp = threadIdx.x >> 5, lane = threadIdx.x & 31;
    int prow0 = ch * BROWS + warp * RW;
    const float4* xb = reinterpret_cast<const float4*>(x) + ((size_t)b * Cv + prow0) * N4v;
    bool tail = (lane < 4);

    float4 acc[Mv][7];
#pragma unroll
    for (int m = 0; m < Mv; ++m)
#pragma unroll
        for (int k = 0; k < 7; ++k) acc[m][k] = make_float4(0.f, 0.f, 0.f, 0.f);

#pragma unroll 2
    for (int r = 0; r < RW; ++r) {
        const float4* row = xb + (size_t)r * N4v;
        float4 v0 = row[lane];
        float4 v1 = row[lane + 32];
        float4 v2 = row[lane + 64];
        float4 v3 = row[lane + 96];
        float4 v4 = row[lane + 128];
        float4 v5 = row[lane + 160];
        float4 v6 = tail ? row[lane + 192] : make_float4(0.f, 0.f, 0.f, 0.f);

        float s = v0.x*v0.x + v0.y*v0.y + v0.z*v0.z + v0.w*v0.w
                + v1.x*v1.x + v1.y*v1.y + v1.z*v1.z + v1.w*v1.w
                + v2.x*v2.x + v2.y*v2.y + v2.z*v2.z + v2.w*v2.w
                + v3.x*v3.x + v3.y*v3.y + v3.z*v3.z + v3.w*v3.w
                + v4.x*v4.x + v4.y*v4.y + v4.z*v4.z + v4.w*v4.w
                + v5.x*v5.x + v5.y*v5.y + v5.z*v5.z + v5.w*v5.w
                + v6.x*v6.x + v6.y*v6.y + v6.z*v6.z + v6.w*v6.w;
#pragma unroll
        for (int o = 16; o; o >>= 1) s += __shfl_xor_sync(0xffffffffu, s, o);

        float inv = 1.0f / fmaxf(sqrtf(s), 1e-10f);
        int p = prow0 + r;
        if (lane == 0) g_invnorm[b][p] = inv;

        // wsc: 4 scalars (uniform per warp, L1-broadcast loads)
        float w0 = Wm[p]          * inv;
        float w1 = Wm[Cv + p]     * inv;
        float w2 = Wm[2 * Cv + p] * inv;
        float w3 = Wm[3 * Cv + p] * inv;

#pragma unroll
        for (int k = 0; k < 7; ++k) {
            float4 v = (k == 0) ? v0 : (k == 1) ? v1 : (k == 2) ? v2 :
                       (k == 3) ? v3 : (k == 4) ? v4 : (k == 5) ? v5 : v6;
            acc[0][k].x = fmaf(w0, v.x, acc[0][k].x);
            acc[0][k].y = fmaf(w0, v.y, acc[0][k].y);
            acc[0][k].z = fmaf(w0, v.z, acc[0][k].z);
            acc[0][k].w = fmaf(w0, v.w, acc[0][k].w);
            acc[1][k].x = fmaf(w1, v.x, acc[1][k].x);
            acc[1][k].y = fmaf(w1, v.y, acc[1][k].y);
            acc[1][k].z = fmaf(w1, v.z, acc[1][k].z);
            acc[1][k].w = fmaf(w1, v.w, acc[1][k].w);
            acc[2][k].x = fmaf(w2, v.x, acc[2][k].x);
            acc[2][k].y = fmaf(w2, v.y, acc[2][k].y);
            acc[2][k].z = fmaf(w2, v.z, acc[2][k].z);
            acc[2][k].w = fmaf(w2, v.w, acc[2][k].w);
            acc[3][k].x = fmaf(w3, v.x, acc[3][k].x);
            acc[3][k].y = fmaf(w3, v.y, acc[3][k].y);
            acc[3][k].z = fmaf(w3, v.z, acc[3][k].z);
            acc[3][k].w = fmaf(w3, v.w, acc[3][k].w);
        }
    }

    // ---- epilogue: per-warp acc -> smem, block reduce, atomic flush ----
    float4* sa = sdyn + warp * (Mv * N4v);
#pragma unroll
    for (int m = 0; m < Mv; ++m) {
#pragma unroll
        for (int k = 0; k < 7; ++k) {
            int q = lane + 32 * k;
            if (k < 6 || tail) sa[m * N4v + q] = acc[m][k];
        }
    }
    __syncthreads();
    for (int e = threadIdx.x; e < Mv * N4v; e += 128) {
        float4 x0 = sdyn[e];
        float4 x1 = sdyn[Mv * N4v + e];
        float4 x2 = sdyn[2 * Mv * N4v + e];
        float4 x3 = sdyn[3 * Mv * N4v + e];
        float4 sum;
        sum.x = x0.x + x1.x + x2.x + x3.x;
        sum.y = x0.y + x1.y + x2.y + x3.y;
        sum.z = x0.z + x1.z + x2.z + x3.z;
        sum.w = x0.w + x1.w + x2.w + x3.w;
        float* dst = reinterpret_cast<float*>(&g_t[b][0][0]) + e * 4;
        atomicAdd(dst + 0, sum.x);
        atomicAdd(dst + 1, sum.y);
        atomicAdd(dst + 2, sum.z);
        atomicAdd(dst + 3, sum.w);
    }
}

// ---------------------------------------------------------------------------
// kC: one block per b, 224 threads. Sigmoid, per-model sum of g^2,
// h = sum_m g/s; then RE-ZERO g_t for the next call.
// ---------------------------------------------------------------------------
__global__ void __launch_bounds__(224) kC() {
    int b = blockIdx.x;
    int t = threadIdx.x;
    bool valid = (t < N4v);
    float4 gg0 = {0,0,0,0}, gg1 = gg0, gg2 = gg0, gg3 = gg0;
    if (valid) {
        float4 t0 = g_t[b][0][t], t1 = g_t[b][1][t];
        float4 t2 = g_t[b][2][t], t3 = g_t[b][3][t];
        auto sig4 = [](float4 v) {
            float4 r;
            r.x = 1.f / (1.f + __expf(-v.x));
            r.y = 1.f / (1.f + __expf(-v.y));
            r.z = 1.f / (1.f + __expf(-v.z));
            r.w = 1.f / (1.f + __expf(-v.w));
            return r;
        };
        gg0 = sig4(t0); gg1 = sig4(t1); gg2 = sig4(t2); gg3 = sig4(t3);
    }
    float s0 = gg0.x*gg0.x + gg0.y*gg0.y + gg0.z*gg0.z + gg0.w*gg0.w;
    float s1 = gg1.x*gg1.x + gg1.y*gg1.y + gg1.z*gg1.z + gg1.w*gg1.w;
    float s2 = gg2.x*gg2.x + gg2.y*gg2.y + gg2.z*gg2.z + gg2.w*gg2.w;
    float s3 = gg3.x*gg3.x + gg3.y*gg3.y + gg3.z*gg3.z + gg3.w*gg3.w;
#pragma unroll
    for (int o = 16; o; o >>= 1) {
        s0 += __shfl_xor_sync(0xffffffffu, s0, o);
        s1 += __shfl_xor_sync(0xffffffffu, s1, o);
        s2 += __shfl_xor_sync(0xffffffffu, s2, o);
        s3 += __shfl_xor_sync(0xffffffffu, s3, o);
    }
    __shared__ float sm[4];
    if (t < 4) sm[t] = 0.f;
    __syncthreads();
    if ((t & 31) == 0) {
        atomicAdd(&sm[0], s0);
        atomicAdd(&sm[1], s1);
        atomicAdd(&sm[2], s2);
        atomicAdd(&sm[3], s3);
    }
    __syncthreads();
    if (valid) {
        float i0 = 1.f / sm[0], i1 = 1.f / sm[1], i2 = 1.f / sm[2], i3 = 1.f / sm[3];
        float4 h;
        h.x = gg0.x*i0 + gg1.x*i1 + gg2.x*i2 + gg3.x*i3;
        h.y = gg0.y*i0 + gg1.y*i1 + gg2.y*i2 + gg3.y*i3;
        h.z = gg0.z*i0 + gg1.z*i1 + gg2.z*i2 + gg3.z*i3;
        h.w = gg0.w*i0 + gg1.w*i1 + gg2.w*i2 + gg3.w*i3;
        g_h[b][t] = h;
        float4 z = {0, 0, 0, 0};
        g_t[b][0][t] = z; g_t[b][1][t] = z;
        g_t[b][2][t] = z; g_t[b][3][t] = z;
    }
}

// ---------------------------------------------------------------------------
// kD: barrier-free final dot (proven). Grid (32, 32), 512 threads; each
// warp streams TWO rows interleaved; h via __ldg (L1-hot).
// ---------------------------------------------------------------------------
__global__ void __launch_bounds__(512) kD(const float* __restrict__ x,
                                          float* __restrict__ out) {
    int b = blockIdx.x;
    int warp = threadIdx.x >> 5, lane = threadIdx.x & 31;
    int p = (blockIdx.y << 5) + (warp << 1);   // rows p and p+1
    const float4* r0 = reinterpret_cast<const float4*>(x) + ((size_t)b * Cv + p) * N4v;
    const float4* r1 = r0 + N4v;
    const float4* hb = &g_h[b][0];
    float s0 = 0.f, s1 = 0.f;
#pragma unroll
    for (int k = 0; k < 6; ++k) {
        int idx = lane + k * 32;
        float4 a = r0[idx], c = r1[idx];
        float4 h = __ldg(hb + idx);
        s0 += a.x * h.x + a.y * h.y + a.z * h.z + a.w * h.w;
        s1 += c.x * h.x + c.y * h.y + c.z * h.z + c.w * h.w;
    }
    if (lane < 4) {
        int idx = 192 + lane;
        float4 a = r0[idx], c = r1[idx];
        float4 h = __ldg(hb + idx);
        s0 += a.x * h.x + a.y * h.y + a.z * h.z + a.w * h.w;
        s1 += c.x * h.x + c.y * h.y + c.z * h.z + c.w * h.w;
    }
#pragma unroll
    for (int o = 16; o; o >>= 1) {
        s0 += __shfl_xor_sync(0xffffffffu, s0, o);
        s1 += __shfl_xor_sync(0xffffffffu, s1, o);
    }
    if (lane == 0) {
        out[b * Cv + p]     = s0 * g_invnorm[b][p];
        out[b * Cv + p + 1] = s1 * g_invnorm[b][p + 1];
    }
}

extern "C" void kernel_launch(void* const* d_in, const int* in_sizes, int n_in,
                              void* d_out, int out_size) {
    const float* x  = (const float*)d_in[0];   // [32,1024,28,28] f32
    const float* Wm = (const float*)d_in[1];   // [4,1,1024] f32
    float* out = (float*)d_out;                // [32,1024] f32

    static const int smem_bytes = WB * Mv * N4v * sizeof(float4);  // 50176
    cudaFuncSetAttribute(kAB, cudaFuncAttributeMaxDynamicSharedMemorySize, smem_bytes);

    kAB<<<dim3(32, CHUNKS), 128, smem_bytes>>>(x, Wm);
    kC<<<32, 224>>>();
    kD<<<dim3(32, 32), 512>>>(x, out);
}

// round 13
// speedup vs baseline: 1.9366x; 1.9366x over previous
#include <cuda_runtime.h>
#include <cstdint>

// Problem dims
#define Bv 32
#define Cv 1024
#define Nv 784
#define Mv 4
#define N4v 196      // Nv/4
#define GR 8         // rows per generation
#define GEN 8        // generations per block
#define BROWS 64     // GR*GEN rows per block
#define CHUNKS 16    // Cv/BROWS
#define GSZ (GR * N4v)   // 1568 float4 per generation buffer

// Scratch (device globals — zero-initialized at load; kC restores zeros)
__device__ float  g_invnorm[Bv][Cv];
__device__ float4 g_t[Bv][Mv][N4v];   // RED-accumulated t (400 KB)
__device__ float4 g_h[Bv][N4v];       // h[b,n] = sum_m g/s

__device__ __forceinline__ void cp_async16(uint32_t saddr, const void* gaddr) {
    asm volatile("cp.async.cg.shared.global [%0], [%1], 16;\n" :: "r"(saddr), "l"(gaddr));
}
__device__ __forceinline__ void cp_commit() {
    asm volatile("cp.async.commit_group;\n");
}
template <int N>
__device__ __forceinline__ void cp_wait() {
    asm volatile("cp.async.wait_group %0;\n" :: "n"(N));
}

extern __shared__ float4 smem_dyn[];  // 2 * GSZ float4 = 50176 B

// ---------------------------------------------------------------------------
// kAB: block = (b, 64-row chunk), 8 generations of 8 rows, double-buffered
// cp.async (R9/R3 proven pipeline). Per gen: warp-per-row norms from smem,
// then thread-per-quad 8-row accumulate. ONE RED-atomic flush per block
// (halved atomic count vs R9: 1.6M total).
// ---------------------------------------------------------------------------
__global__ void __launch_bounds__(256) kAB(const float* __restrict__ x,
                                           const float* __restrict__ Wm) {
    __shared__ float4 swsc[GR];
    int b = blockIdx.x, ch = blockIdx.y;
    int p0 = ch * BROWS;
    int t = threadIdx.x;
    int warp = t >> 5, lane = t & 31;
    const float4* base = reinterpret_cast<const float4*>(x) + ((size_t)b * Cv + p0) * N4v;
    uint32_t sbase = (uint32_t)__cvta_generic_to_shared(smem_dyn);

    // prefetch generation 0 into buffer 0
#pragma unroll
    for (int k = 0; k < 7; ++k) {
        int i = t + k * 256;
        if (i < GSZ) cp_async16(sbase + i * 16u, base + i);
    }
    cp_commit();

    float4 a0 = {0, 0, 0, 0}, a1 = a0, a2 = a0, a3 = a0;

#pragma unroll
    for (int g = 0; g < GEN; ++g) {
        if (g + 1 < GEN) {
            uint32_t sb = sbase + ((g + 1) & 1) * (GSZ * 16u);
            const float4* gb = base + (g + 1) * GSZ;
#pragma unroll
            for (int k = 0; k < 7; ++k) {
                int i = t + k * 256;
                if (i < GSZ) cp_async16(sb + i * 16u, gb + i);
            }
            cp_commit();
            cp_wait<1>();   // current generation's data is ready
        } else {
            cp_wait<0>();
        }
        __syncthreads();

        float4* cur = smem_dyn + (g & 1) * GSZ;

        // norms: warp w handles row w (8 warps, 8 rows)
        {
            float s = 0.f;
#pragma unroll
            for (int k = 0; k < 7; ++k) {
                int idx = lane + k * 32;
                if (idx < N4v) {
                    float4 v = cur[warp * N4v + idx];
                    s += v.x * v.x + v.y * v.y + v.z * v.z + v.w * v.w;
                }
            }
#pragma unroll
            for (int o = 16; o; o >>= 1) s += __shfl_xor_sync(0xffffffffu, s, o);
            if (lane == 0) {
                float inv = 1.0f / fmaxf(sqrtf(s), 1e-10f);
                int p = p0 + g * GR + warp;
                g_invnorm[b][p] = inv;
                float4 w;
                w.x = Wm[0 * Cv + p] * inv;
                w.y = Wm[1 * Cv + p] * inv;
                w.z = Wm[2 * Cv + p] * inv;
                w.w = Wm[3 * Cv + p] * inv;
                swsc[warp] = w;
            }
        }
        __syncthreads();

        // t-accumulation for this generation's 8 rows
        if (t < N4v) {
#pragma unroll
            for (int r = 0; r < GR; ++r) {
                float4 w  = swsc[r];
                float4 xv = cur[r * N4v + t];
                a0.x = fmaf(w.x, xv.x, a0.x); a0.y = fmaf(w.x, xv.y, a0.y);
                a0.z = fmaf(w.x, xv.z, a0.z); a0.w = fmaf(w.x, xv.w, a0.w);
                a1.x = fmaf(w.y, xv.x, a1.x); a1.y = fmaf(w.y, xv.y, a1.y);
                a1.z = fmaf(w.y, xv.z, a1.z); a1.w = fmaf(w.y, xv.w, a1.w);
                a2.x = fmaf(w.z, xv.x, a2.x); a2.y = fmaf(w.z, xv.y, a2.y);
                a2.z = fmaf(w.z, xv.z, a2.z); a2.w = fmaf(w.z, xv.w, a2.w);
                a3.x = fmaf(w.w, xv.x, a3.x); a3.y = fmaf(w.w, xv.y, a3.y);
                a3.z = fmaf(w.w, xv.z, a3.z); a3.w = fmaf(w.w, xv.w, a3.w);
            }
        }
        __syncthreads();  // buffer fully consumed before next prefetch overwrites
    }

    if (t < N4v) {
        float* d0 = reinterpret_cast<float*>(&g_t[b][0][t]);
        float* d1 = reinterpret_cast<float*>(&g_t[b][1][t]);
        float* d2 = reinterpret_cast<float*>(&g_t[b][2][t]);
        float* d3 = reinterpret_cast<float*>(&g_t[b][3][t]);
        atomicAdd(d0 + 0, a0.x); atomicAdd(d0 + 1, a0.y);
        atomicAdd(d0 + 2, a0.z); atomicAdd(d0 + 3, a0.w);
        atomicAdd(d1 + 0, a1.x); atomicAdd(d1 + 1, a1.y);
        atomicAdd(d1 + 2, a1.z); atomicAdd(d1 + 3, a1.w);
        atomicAdd(d2 + 0, a2.x); atomicAdd(d2 + 1, a2.y);
        atomicAdd(d2 + 2, a2.z); atomicAdd(d2 + 3, a2.w);
        atomicAdd(d3 + 0, a3.x); atomicAdd(d3 + 1, a3.y);
        atomicAdd(d3 + 2, a3.z); atomicAdd(d3 + 3, a3.w);
    }
}

// ---------------------------------------------------------------------------
// kC: one block per b, 224 threads. Sigmoid, per-model sum of g^2,
// h = sum_m g/s; then RE-ZERO g_t for the next call.
// ---------------------------------------------------------------------------
__global__ void __launch_bounds__(224) kC() {
    int b = blockIdx.x;
    int t = threadIdx.x;
    bool valid = (t < N4v);
    float4 gg0 = {0,0,0,0}, gg1 = gg0, gg2 = gg0, gg3 = gg0;
    if (valid) {
        float4 t0 = g_t[b][0][t], t1 = g_t[b][1][t];
        float4 t2 = g_t[b][2][t], t3 = g_t[b][3][t];
        auto sig4 = [](float4 v) {
            float4 r;
            r.x = 1.f / (1.f + __expf(-v.x));
            r.y = 1.f / (1.f + __expf(-v.y));
            r.z = 1.f / (1.f + __expf(-v.z));
            r.w = 1.f / (1.f + __expf(-v.w));
            return r;
        };
        gg0 = sig4(t0); gg1 = sig4(t1); gg2 = sig4(t2); gg3 = sig4(t3);
    }
    float s0 = gg0.x*gg0.x + gg0.y*gg0.y + gg0.z*gg0.z + gg0.w*gg0.w;
    float s1 = gg1.x*gg1.x + gg1.y*gg1.y + gg1.z*gg1.z + gg1.w*gg1.w;
    float s2 = gg2.x*gg2.x + gg2.y*gg2.y + gg2.z*gg2.z + gg2.w*gg2.w;
    float s3 = gg3.x*gg3.x + gg3.y*gg3.y + gg3.z*gg3.z + gg3.w*gg3.w;
#pragma unroll
    for (int o = 16; o; o >>= 1) {
        s0 += __shfl_xor_sync(0xffffffffu, s0, o);
        s1 += __shfl_xor_sync(0xffffffffu, s1, o);
        s2 += __shfl_xor_sync(0xffffffffu, s2, o);
        s3 += __shfl_xor_sync(0xffffffffu, s3, o);
    }
    __shared__ float sm[4];
    if (t < 4) sm[t] = 0.f;
    __syncthreads();
    if ((t & 31) == 0) {
        atomicAdd(&sm[0], s0);
        atomicAdd(&sm[1], s1);
        atomicAdd(&sm[2], s2);
        atomicAdd(&sm[3], s3);
    }
    __syncthreads();
    if (valid) {
        float i0 = 1.f / sm[0], i1 = 1.f / sm[1], i2 = 1.f / sm[2], i3 = 1.f / sm[3];
        float4 h;
        h.x = gg0.x*i0 + gg1.x*i1 + gg2.x*i2 + gg3.x*i3;
        h.y = gg0.y*i0 + gg1.y*i1 + gg2.y*i2 + gg3.y*i3;
        h.z = gg0.z*i0 + gg1.z*i1 + gg2.z*i2 + gg3.z*i3;
        h.w = gg0.w*i0 + gg1.w*i1 + gg2.w*i2 + gg3.w*i3;
        g_h[b][t] = h;
        float4 z = {0, 0, 0, 0};
        g_t[b][0][t] = z; g_t[b][1][t] = z;
        g_t[b][2][t] = z; g_t[b][3][t] = z;
    }
}

// ---------------------------------------------------------------------------
// kD: barrier-free final dot (proven). Grid (32, 32), 512 threads; each
// warp streams TWO rows interleaved; h via __ldg (L1-hot).
// ---------------------------------------------------------------------------
__global__ void __launch_bounds__(512) kD(const float* __restrict__ x,
                                          float* __restrict__ out) {
    int b = blockIdx.x;
    int warp = threadIdx.x >> 5, lane = threadIdx.x & 31;
    int p = (blockIdx.y << 5) + (warp << 1);   // rows p and p+1
    const float4* r0 = reinterpret_cast<const float4*>(x) + ((size_t)b * Cv + p) * N4v;
    const float4* r1 = r0 + N4v;
    const float4* hb = &g_h[b][0];
    float s0 = 0.f, s1 = 0.f;
#pragma unroll
    for (int k = 0; k < 6; ++k) {
        int idx = lane + k * 32;
        float4 a = r0[idx], c = r1[idx];
        float4 h = __ldg(hb + idx);
        s0 += a.x * h.x + a.y * h.y + a.z * h.z + a.w * h.w;
        s1 += c.x * h.x + c.y * h.y + c.z * h.z + c.w * h.w;
    }
    if (lane < 4) {
        int idx = 192 + lane;
        float4 a = r0[idx], c = r1[idx];
        float4 h = __ldg(hb + idx);
        s0 += a.x * h.x + a.y * h.y + a.z * h.z + a.w * h.w;
        s1 += c.x * h.x + c.y * h.y + c.z * h.z + c.w * h.w;
    }
#pragma unroll
    for (int o = 16; o; o >>= 1) {
        s0 += __shfl_xor_sync(0xffffffffu, s0, o);
        s1 += __shfl_xor_sync(0xffffffffu, s1, o);
    }
    if (lane == 0) {
        out[b * Cv + p]     = s0 * g_invnorm[b][p];
        out[b * Cv + p + 1] = s1 * g_invnorm[b][p + 1];
    }
}

extern "C" void kernel_launch(void* const* d_in, const int* in_sizes, int n_in,
                              void* d_out, int out_size) {
    const float* x  = (const float*)d_in[0];   // [32,1024,28,28] f32
    const float* Wm = (const float*)d_in[1];   // [4,1,1024] f32
    float* out = (float*)d_out;                // [32,1024] f32

    static const int smem_bytes = 2 * GSZ * sizeof(float4);  // 50176
    cudaFuncSetAttribute(kAB, cudaFuncAttributeMaxDynamicSharedMemorySize, smem_bytes);

    kAB<<<dim3(32, CHUNKS), 256, smem_bytes>>>(x, Wm);
    kC<<<32, 224>>>();
    kD<<<dim3(32, 32), 512>>>(x, out);
}